// round 9
// baseline (speedup 1.0000x reference)
#include <cuda_runtime.h>
#include <cuda_bf16.h>
#include <cstdint>

#define B_    16
#define CIN_  512
#define COUT_ 3
#define WDIM_ 512
#define HW_   16384
#define HW4_  4096

#define FC_GAIN_     0.044194173824159216f
#define WEIGHT_GAIN_ 0.044194173824159216f
#define CLAMP_       256.0f

#define CHUNK_   8
#define NCHUNK_  (CIN_ / CHUNK_)
#define NBLOCKS_ (B_ * (HW4_ / 64))   // 1024

// Per-sample modulated 1x1 conv weights: [B][CIN] x float4 (w_o0, w_o1, w_o2, pad)
__device__ float4 g_wmod[B_ * CIN_];
__device__ unsigned g_count = 0;   // styles blocks published
__device__ unsigned g_done  = 0;   // blocks finished (for graph-replay reset)

__device__ __forceinline__ void cp_async16(uint32_t smem_addr, const void* gptr) {
    asm volatile("cp.async.cg.shared.global [%0], [%1], 16;"
                 :: "r"(smem_addr), "l"(gptr) : "memory");
}

// ---------------------------------------------------------------------------
// Fused kernel. grid = 1024 x 64 threads.
//  1) every block prefetches chunks 0 AND 1 (16 KB in flight -> 16 MB chip)
//  2) every block computes 8 of the 8192 (c,b) style entries:
//     c = bid>>1, batches (bid&1)*8 + warp*4 .. +3  (warp keeps the 3 affine
//     rows in registers across its 4 serial batch dots)
//  3) spin until all 1024 blocks published, load swm, stream conv
// 25 KB smem -> 9 blocks/SM, 1332 slots >= 1024: whole grid co-resident,
// every block makes progress -> no deadlock.
// ---------------------------------------------------------------------------
__global__ __launch_bounds__(64)
void fused_kernel(const float* __restrict__ x,
                  const float* __restrict__ w,
                  const float* __restrict__ aW,
                  const float* __restrict__ ab,
                  const float* __restrict__ cw,
                  const float* __restrict__ cb,
                  float* __restrict__ out) {
    const int bid = blockIdx.x;
    const int t   = threadIdx.x;
    const int b   = bid >> 6;
    const int p   = (bid & 63) * 64 + t;          // float4 pixel index

    __shared__ float4 swm[CIN_];
    __shared__ float4 stage[2][CHUNK_][64];

    const float4* __restrict__ xb =
        reinterpret_cast<const float4*>(x) + (size_t)b * CIN_ * HW4_ + p;

    const uint32_t stbase = (uint32_t)__cvta_generic_to_shared(&stage[0][0][t]);

    // ---- 1) prologue prefetch: chunk 0 -> buf0, chunk 1 -> buf1 ----
#pragma unroll
    for (int i = 0; i < CHUNK_; i++)
        cp_async16(stbase + i * 1024, xb + (size_t)i * HW4_);
    asm volatile("cp.async.commit_group;" ::: "memory");
#pragma unroll
    for (int i = 0; i < CHUNK_; i++)
        cp_async16(stbase + (CHUNK_ * 1024) + i * 1024,
                   xb + (size_t)(CHUNK_ + i) * HW4_);
    asm volatile("cp.async.commit_group;" ::: "memory");

    // ---- 2) styles: 8 (c,b) pairs per block ----
    {
        const int c    = bid >> 1;
        const int warp = t >> 5;            // 0..1
        const int lane = t & 31;
        const int bs   = (bid & 1) * 8 + warp * 4;   // first of 4 batches

        const float4* __restrict__ r0 = reinterpret_cast<const float4*>(aW + (size_t)(0 * CIN_ + c) * WDIM_);
        const float4* __restrict__ r1 = reinterpret_cast<const float4*>(aW + (size_t)(1 * CIN_ + c) * WDIM_);
        const float4* __restrict__ r2 = reinterpret_cast<const float4*>(aW + (size_t)(2 * CIN_ + c) * WDIM_);

        float4 R0[4], R1[4], R2[4];
#pragma unroll
        for (int i = 0; i < 4; i++) {
            const int j = i * 32 + lane;
            R0[i] = r0[j];
            R1[i] = r1[j];
            R2[i] = r2[j];
        }

#pragma unroll
        for (int bb = 0; bb < 4; bb++) {
            const int bw = bs + bb;
            const float4* __restrict__ w4 =
                reinterpret_cast<const float4*>(w + (size_t)bw * WDIM_);

            float s0 = 0.f, s1 = 0.f, s2 = 0.f;
#pragma unroll
            for (int i = 0; i < 4; i++) {
                float4 wv = w4[i * 32 + lane];
                s0 += wv.x * R0[i].x + wv.y * R0[i].y + wv.z * R0[i].z + wv.w * R0[i].w;
                s1 += wv.x * R1[i].x + wv.y * R1[i].y + wv.z * R1[i].z + wv.w * R1[i].w;
                s2 += wv.x * R2[i].x + wv.y * R2[i].y + wv.z * R2[i].z + wv.w * R2[i].w;
            }
#pragma unroll
            for (int off = 16; off > 0; off >>= 1) {
                s0 += __shfl_xor_sync(0xFFFFFFFF, s0, off);
                s1 += __shfl_xor_sync(0xFFFFFFFF, s1, off);
                s2 += __shfl_xor_sync(0xFFFFFFFF, s2, off);
            }
            if (lane == 0) {
                float m1 = s0 * FC_GAIN_ + ab[0 * CIN_ + c];
                float m2 = s1 * FC_GAIN_ + ab[1 * CIN_ + c];
                float m3 = s2 * FC_GAIN_ + ab[2 * CIN_ + c];
                float st = (m1 * m2 + m3) * WEIGHT_GAIN_;
                g_wmod[bw * CIN_ + c] = make_float4(cw[0 * CIN_ + c] * st,
                                                    cw[1 * CIN_ + c] * st,
                                                    cw[2 * CIN_ + c] * st,
                                                    0.f);
            }
        }
        __syncthreads();
        if (t == 0) {
            __threadfence();
            atomicAdd(&g_count, 1u);
        }
    }

    // ---- 3) wait for all blocks' styles, then load swm ----
    if (t == 0) {
        unsigned v;
        do {
            asm volatile("ld.acquire.gpu.global.u32 %0, [%1];"
                         : "=r"(v) : "l"(&g_count) : "memory");
        } while (v < NBLOCKS_);
    }
    __syncthreads();

    {
        const float4* gw = g_wmod + b * CIN_;
#pragma unroll
        for (int i = 0; i < CIN_ / 64; i++)
            swm[i * 64 + t] = gw[i * 64 + t];
    }
    __syncthreads();

    // ---- conv main loop: 2-buffer pipeline, 2 chunks prefetched ahead ----
    float4 a0 = make_float4(0.f, 0.f, 0.f, 0.f);
    float4 a1 = a0;
    float4 a2 = a0;

    for (int k = 0; k < NCHUNK_; k++) {
        const int cur = k & 1;
        if (k >= 1 && k + 1 < NCHUNK_) {
            // refill the buffer consumed last iteration with chunk k+1
            const int c1 = (k + 1) * CHUNK_;
            const uint32_t sb = stbase + ((k + 1) & 1) * (CHUNK_ * 1024);
#pragma unroll
            for (int i = 0; i < CHUNK_; i++)
                cp_async16(sb + i * 1024, xb + (size_t)(c1 + i) * HW4_);
            asm volatile("cp.async.commit_group;" ::: "memory");
        }
        if (k + 1 < NCHUNK_) {
            asm volatile("cp.async.wait_group 1;" ::: "memory");
        } else {
            asm volatile("cp.async.wait_group 0;" ::: "memory");
        }

#pragma unroll
        for (int i = 0; i < CHUNK_; i++) {
            float4 xv = stage[cur][i][t];
            float4 wm = swm[k * CHUNK_ + i];
            a0.x = fmaf(xv.x, wm.x, a0.x);
            a0.y = fmaf(xv.y, wm.x, a0.y);
            a0.z = fmaf(xv.z, wm.x, a0.z);
            a0.w = fmaf(xv.w, wm.x, a0.w);
            a1.x = fmaf(xv.x, wm.y, a1.x);
            a1.y = fmaf(xv.y, wm.y, a1.y);
            a1.z = fmaf(xv.z, wm.y, a1.z);
            a1.w = fmaf(xv.w, wm.y, a1.w);
            a2.x = fmaf(xv.x, wm.z, a2.x);
            a2.y = fmaf(xv.y, wm.z, a2.y);
            a2.z = fmaf(xv.z, wm.z, a2.z);
            a2.w = fmaf(xv.w, wm.z, a2.w);
        }
    }

    const float b0 = cb[0], b1 = cb[1], b2 = cb[2];

    a0.x = fminf(fmaxf(a0.x + b0, -CLAMP_), CLAMP_);
    a0.y = fminf(fmaxf(a0.y + b0, -CLAMP_), CLAMP_);
    a0.z = fminf(fmaxf(a0.z + b0, -CLAMP_), CLAMP_);
    a0.w = fminf(fmaxf(a0.w + b0, -CLAMP_), CLAMP_);

    a1.x = fminf(fmaxf(a1.x + b1, -CLAMP_), CLAMP_);
    a1.y = fminf(fmaxf(a1.y + b1, -CLAMP_), CLAMP_);
    a1.z = fminf(fmaxf(a1.z + b1, -CLAMP_), CLAMP_);
    a1.w = fminf(fmaxf(a1.w + b1, -CLAMP_), CLAMP_);

    a2.x = fminf(fmaxf(a2.x + b2, -CLAMP_), CLAMP_);
    a2.y = fminf(fmaxf(a2.y + b2, -CLAMP_), CLAMP_);
    a2.z = fminf(fmaxf(a2.z + b2, -CLAMP_), CLAMP_);
    a2.w = fminf(fmaxf(a2.w + b2, -CLAMP_), CLAMP_);

    float4* __restrict__ o =
        reinterpret_cast<float4*>(out) + (size_t)b * COUT_ * HW4_ + p;
    o[0 * HW4_] = a0;
    o[1 * HW4_] = a1;
    o[2 * HW4_] = a2;

    // ---- reset flags for the next graph replay (last block out) ----
    __syncthreads();
    if (t == 0) {
        __threadfence();
        unsigned d = atomicAdd(&g_done, 1u);
        if (d == NBLOCKS_ - 1) {
            g_count = 0;
            g_done  = 0;
            __threadfence();
        }
    }
}

// ---------------------------------------------------------------------------
// inputs (metadata order): x, w, affine_W, affine_b, conv_w, conv_b
// ---------------------------------------------------------------------------
extern "C" void kernel_launch(void* const* d_in, const int* in_sizes, int n_in,
                              void* d_out, int out_size) {
    const float* x  = (const float*)d_in[0];
    const float* w  = (const float*)d_in[1];
    const float* aW = (const float*)d_in[2];
    const float* ab = (const float*)d_in[3];
    const float* cw = (const float*)d_in[4];
    const float* cb = (const float*)d_in[5];
    float* out = (float*)d_out;

    fused_kernel<<<NBLOCKS_, 64>>>(x, w, aW, ab, cw, cb, out);
}